// round 14
// baseline (speedup 1.0000x reference)
#include <cuda_runtime.h>
#include <cuda_bf16.h>
#include <math.h>
#include <stdint.h>

#define T_LEN 160
#define B_SZ  640
#define IN_F  40
#define H_SZ  256
#define G_SZ  1024
#define N_SPK 64
#define M_UTT 10

#define NBT   8        // batch tiles (recurrence)
#define BT    80       // batch rows per block
#define NCT   16       // col tiles
#define GP    68       // gate smem pitch (floats)
#define PT    320      // persistent kernel threads (10 warps)
#define WPB   132      // word pitch for bf16-pair planes (128 pairs + pad)
#define CP    20       // bulk chunk word pitch (16 words + 4 pad)

// ---------------- device scratch --------------------------------------------
static __device__ float g_Xg[(size_t)T_LEN * B_SZ * G_SZ];            // fp32 input gates
static __device__ unsigned short g_hhi[(size_t)T_LEN * B_SZ * H_SZ];  // bf16 hi h plane
static __device__ unsigned short g_hlo[(size_t)T_LEN * B_SZ * H_SZ];  // bf16 lo h plane
static __device__ unsigned short g_shi[(size_t)T_LEN * B_SZ * 64];    // layer0 seq hi (P=64)
static __device__ unsigned short g_slo[(size_t)T_LEN * B_SZ * 64];    // layer0 seq lo
static __device__ unsigned short g_Wbh[G_SZ * H_SZ];                  // W hi plane
static __device__ unsigned short g_Wbl[G_SZ * H_SZ];                  // W lo plane
static __device__ float g_c[B_SZ * H_SZ];
static __device__ float g_E1[B_SZ * H_SZ];
static __device__ float g_En[B_SZ * H_SZ];
static __device__ float g_C[N_SPK * H_SZ];
static __device__ float g_Cn[N_SPK * H_SZ];
static __device__ float g_d[B_SZ];
static __device__ unsigned int g_flag[NBT][NCT];   // distributed step flags (epoch-valued)

// ---------------- helpers ---------------------------------------------------
__device__ __forceinline__ void mma_bf16(float* d, const uint32_t* a,
                                         uint32_t b0, uint32_t b1) {
    asm volatile(
        "mma.sync.aligned.m16n8k16.row.col.f32.bf16.bf16.f32 "
        "{%0,%1,%2,%3}, {%4,%5,%6,%7}, {%8,%9}, {%0,%1,%2,%3};"
        : "+f"(d[0]), "+f"(d[1]), "+f"(d[2]), "+f"(d[3])
        : "r"(a[0]), "r"(a[1]), "r"(a[2]), "r"(a[3]), "r"(b0), "r"(b1));
}

__device__ __forceinline__ void bf16_split(float v, unsigned short& hi, unsigned short& lo) {
    __nv_bfloat16 h = __float2bfloat16(v);
    __nv_bfloat16 l = __float2bfloat16(v - __bfloat162float(h));
    hi = __bfloat16_as_ushort(h);
    lo = __bfloat16_as_ushort(l);
}

__device__ __forceinline__ float block_sum(float v, float* sh) {
    int tid = threadIdx.x;
    #pragma unroll
    for (int o = 16; o > 0; o >>= 1) v += __shfl_down_sync(0xffffffffu, v, o);
    if ((tid & 31) == 0) sh[tid >> 5] = v;
    __syncthreads();
    int nw = blockDim.x >> 5;
    float r = (tid < nw) ? sh[tid] : 0.f;
    if (tid < 32) {
        #pragma unroll
        for (int o = 16; o > 0; o >>= 1) r += __shfl_down_sync(0xffffffffu, r, o);
        if (tid == 0) sh[0] = r;
    }
    __syncthreads();
    float out = sh[0];
    __syncthreads();
    return out;
}

__device__ __forceinline__ float sigf(float x) { return 1.f / (1.f + __expf(-x)); }

__global__ void reset_flags_kernel() {
    if (threadIdx.x < NBT * NCT) ((unsigned int*)g_flag)[threadIdx.x] = 0u;
}

// ---------------- bf16 packers ----------------------------------------------
__global__ void split_w_kernel(const float* __restrict__ W, int K, int P) {
    int idx = blockIdx.x * 256 + threadIdx.x;
    if (idx >= G_SZ * P) return;
    int row = idx / P, k = idx - row * P;
    float v = (k < K) ? W[row * K + k] : 0.f;
    unsigned short hi, lo;
    bf16_split(v, hi, lo);
    g_Wbh[idx] = hi;
    g_Wbl[idx] = lo;
}

__global__ void split_seq_kernel(const float* __restrict__ seq) {
    size_t idx = (size_t)blockIdx.x * 256 + threadIdx.x;
    if (idx >= (size_t)T_LEN * B_SZ * 64) return;
    int row = (int)(idx >> 6), k = (int)(idx & 63);
    float v = 0.f;
    if (k < IN_F) {
        int t = row / B_SZ, b = row - t * B_SZ;
        v = seq[(size_t)b * (T_LEN * IN_F) + (size_t)t * IN_F + k];
    }
    unsigned short hi, lo;
    bf16_split(v, hi, lo);
    g_shi[idx] = hi;
    g_slo[idx] = lo;
}

// ---------------- bulk GEMM, 3-term bf16 (unchanged from R13) ---------------
__global__ void __launch_bounds__(256)
bulk_bf16_kernel(const float* __restrict__ bih,
                 const float* __restrict__ bhh,
                 int P, int src_mode)
{
    __shared__ __align__(16) uint32_t Ahi[128 * CP], Alo[128 * CP];
    __shared__ __align__(16) uint32_t Bh[64 * CP],  Bl[64 * CP];

    const int tid  = threadIdx.x;
    const int warp = tid >> 5;
    const int lane = tid & 31;
    const int gid  = lane >> 2;
    const int tig  = lane & 3;
    const int row0 = blockIdx.y * 128;
    const int col0 = blockIdx.x * 64;
    const int m0   = warp * 16;

    const unsigned short* Ahg = (src_mode == 0) ? g_shi : g_hhi;
    const unsigned short* Alg = (src_mode == 0) ? g_slo : g_hlo;

    float acc[8][4];
    #pragma unroll
    for (int s = 0; s < 8; s++)
        #pragma unroll
        for (int j = 0; j < 4; j++) acc[s][j] = 0.f;

    for (int kc = 0; kc < P; kc += 32) {
        #pragma unroll
        for (int i = 0; i < 2; i++) {
            int slot = tid + i * 256;
            int r = slot >> 2, q = slot & 3;
            size_t src = (size_t)(row0 + r) * P + kc + q * 8;
            ((uint4*)&Ahi[r * CP])[q] = *(const uint4*)&Ahg[src];
            ((uint4*)&Alo[r * CP])[q] = *(const uint4*)&Alg[src];
        }
        {
            int r = tid >> 2, q = tid & 3;
            size_t src = (size_t)(col0 + r) * P + kc + q * 8;
            ((uint4*)&Bh[r * CP])[q] = *(const uint4*)&g_Wbh[src];
            ((uint4*)&Bl[r * CP])[q] = *(const uint4*)&g_Wbl[src];
        }
        __syncthreads();

        #pragma unroll
        for (int ks = 0; ks < 2; ks++) {
            const int kb = ks * 8;
            uint32_t ah[4], al[4];
            ah[0] = Ahi[(m0 + gid)     * CP + kb + tig];
            ah[1] = Ahi[(m0 + gid + 8) * CP + kb + tig];
            ah[2] = Ahi[(m0 + gid)     * CP + kb + tig + 4];
            ah[3] = Ahi[(m0 + gid + 8) * CP + kb + tig + 4];
            al[0] = Alo[(m0 + gid)     * CP + kb + tig];
            al[1] = Alo[(m0 + gid + 8) * CP + kb + tig];
            al[2] = Alo[(m0 + gid)     * CP + kb + tig + 4];
            al[3] = Alo[(m0 + gid + 8) * CP + kb + tig + 4];
            #pragma unroll
            for (int sub = 0; sub < 8; sub++) {
                int n = sub * 8 + gid;
                uint32_t bh0 = Bh[n * CP + kb + tig];
                uint32_t bh1 = Bh[n * CP + kb + tig + 4];
                uint32_t bl0 = Bl[n * CP + kb + tig];
                uint32_t bl1 = Bl[n * CP + kb + tig + 4];
                mma_bf16(acc[sub], ah, bh0, bh1);
                mma_bf16(acc[sub], al, bh0, bh1);
                mma_bf16(acc[sub], ah, bl0, bl1);
            }
        }
        __syncthreads();
    }

    #pragma unroll
    for (int sub = 0; sub < 8; sub++) {
        const int col = col0 + sub * 8 + 2 * tig;
        const float bias0 = bih[col] + bhh[col];
        const float bias1 = bih[col + 1] + bhh[col + 1];
        const int r1 = row0 + m0 + gid;
        float2 o1 = {acc[sub][0] + bias0, acc[sub][1] + bias1};
        *(float2*)&g_Xg[(size_t)r1 * G_SZ + col] = o1;
        float2 o2 = {acc[sub][2] + bias0, acc[sub][3] + bias1};
        *(float2*)&g_Xg[(size_t)(r1 + 8) * G_SZ + col] = o2;
    }
}

// ---------------- persistent LSTM recurrence, bf16 3-term -------------------
// R13 kernel + latency-trimmed step barrier:
//   distributed per-block epoch flags, early-arrive / late-wait,
//   Xg[t+1] prefetch issued between arrive and wait (hidden behind skew).
__global__ void __launch_bounds__(PT)
lstm_persistent_kernel(const float* __restrict__ Whh,
                       const int* __restrict__ lens,
                       int epoch_base)
{
    extern __shared__ __align__(16) uint32_t smw[];
    uint32_t* whi = smw;                       // 64*WPB
    uint32_t* wlo = whi + 64 * WPB;
    uint32_t* hhi = wlo + 64 * WPB;            // 80*WPB
    uint32_t* hlo = hhi + 80 * WPB;
    float*    gsm = (float*)hhi;               // overlay (post-MMA staging)

    const int tid  = threadIdx.x;              // 0..319
    const int warp = tid >> 5;
    const int lane = tid & 31;
    const int gid  = lane >> 2;
    const int tig  = lane & 3;
    const int mt   = warp >> 1;
    const int nh   = warp & 1;
    const int m0   = mt * 16;

    const int n0 = blockIdx.x * 16;
    const int b0 = blockIdx.y * BT;
    const int cb = blockIdx.x;                 // col-block index
    const int bt = blockIdx.y;

    const int hnx_c = tid & 15;
    const int bg    = tid >> 4;
    const int hn_c  = n0 + hnx_c;

    // W slice -> smem packed bf16 hi/lo pairs; col c = hx*4 + g
    for (int lin = tid; lin < 64 * 128; lin += PT) {
        int kp = lin & 127;
        int c  = lin >> 7;
        int g  = c & 3;
        int hx = c >> 2;
        const float* wr = Whh + (size_t)(g * H_SZ + n0 + hx) * H_SZ + 2 * kp;
        unsigned short h0, l0, h1, l1;
        bf16_split(wr[0], h0, l0);
        bf16_split(wr[1], h1, l1);
        whi[c * WPB + kp] = ((uint32_t)h1 << 16) | h0;
        wlo[c * WPB + kp] = ((uint32_t)l1 << 16) | l0;
    }

    int   len_r[4];
    float c_r[4], h_r[4];
    #pragma unroll
    for (int r = 0; r < 4; r++) {
        len_r[r] = lens[b0 + bg * 4 + r];
        c_r[r] = 0.f;
        h_r[r] = 0.f;
    }

    // prime Xg for t=0
    float xg[4][4];
    #pragma unroll
    for (int r = 0; r < 4; r++) {
        const float* xrow = g_Xg + ((size_t)(b0 + bg * 4 + r)) * G_SZ;
        #pragma unroll
        for (int g = 0; g < 4; g++) xg[r][g] = xrow[g * H_SZ + hn_c];
    }

    __syncthreads();

    for (int t = 0; t < T_LEN; t++) {
        if (t > 0) {
            // ---- load h_{t-1} bf16 planes [80 x 128 words] ----
            const uint4* shi = (const uint4*)(g_hhi + (size_t)(t - 1) * B_SZ * H_SZ);
            const uint4* slo = (const uint4*)(g_hlo + (size_t)(t - 1) * B_SZ * H_SZ);
            #pragma unroll
            for (int i = 0; i < 8; i++) {
                int slot = tid + i * PT;
                int b = slot >> 5;
                int q = slot & 31;
                size_t src = (size_t)(b0 + b) * 32 + q;
                ((uint4*)hhi)[b * 33 + q] = shi[src];
                ((uint4*)hlo)[b * 33 + q] = slo[src];
            }
            __syncthreads();

            float acc[4][4];
            #pragma unroll
            for (int s = 0; s < 4; s++)
                #pragma unroll
                for (int j = 0; j < 4; j++) acc[s][j] = 0.f;

            #pragma unroll 4
            for (int ks = 0; ks < 16; ks++) {
                const int kb = ks * 8;
                uint32_t ah[4], al[4];
                ah[0] = hhi[(m0 + gid)     * WPB + kb + tig];
                ah[1] = hhi[(m0 + gid + 8) * WPB + kb + tig];
                ah[2] = hhi[(m0 + gid)     * WPB + kb + tig + 4];
                ah[3] = hhi[(m0 + gid + 8) * WPB + kb + tig + 4];
                al[0] = hlo[(m0 + gid)     * WPB + kb + tig];
                al[1] = hlo[(m0 + gid + 8) * WPB + kb + tig];
                al[2] = hlo[(m0 + gid)     * WPB + kb + tig + 4];
                al[3] = hlo[(m0 + gid + 8) * WPB + kb + tig + 4];
                #pragma unroll
                for (int s = 0; s < 4; s++) {
                    int n = (nh * 4 + s) * 8 + gid;
                    uint32_t bh0 = whi[n * WPB + kb + tig];
                    uint32_t bh1 = whi[n * WPB + kb + tig + 4];
                    uint32_t bl0 = wlo[n * WPB + kb + tig];
                    uint32_t bl1 = wlo[n * WPB + kb + tig + 4];
                    mma_bf16(acc[s], ah, bh0, bh1);
                    mma_bf16(acc[s], al, bh0, bh1);
                    mma_bf16(acc[s], ah, bl0, bl1);
                }
            }
            __syncthreads();

            #pragma unroll
            for (int s = 0; s < 4; s++) {
                int nc = (nh * 4 + s) * 8 + 2 * tig;
                float2 o1 = {acc[s][0], acc[s][1]};
                float2 o2 = {acc[s][2], acc[s][3]};
                *(float2*)&gsm[(m0 + gid)     * GP + nc] = o1;
                *(float2*)&gsm[(m0 + gid + 8) * GP + nc] = o2;
            }
            __syncthreads();
        }

        // ---- cell phase (c/h register-resident); h emitted as bf16 planes ----
        unsigned short* hhi_out = g_hhi + (size_t)t * B_SZ * H_SZ;
        unsigned short* hlo_out = g_hlo + (size_t)t * B_SZ * H_SZ;
        #pragma unroll
        for (int r = 0; r < 4; r++) {
            const int b = b0 + bg * 4 + r;
            const bool valid = (t < len_r[r]);
            float gi, gf, gg, go;
            if (t > 0) {
                float4 gv = *(const float4*)&gsm[(bg * 4 + r) * GP + hnx_c * 4];
                gi = gv.x + xg[r][0];
                gf = gv.y + xg[r][1];
                gg = gv.z + xg[r][2];
                go = gv.w + xg[r][3];
            } else {
                gi = xg[r][0]; gf = xg[r][1]; gg = xg[r][2]; go = xg[r][3];
            }
            float cn = sigf(gf) * c_r[r] + sigf(gi) * tanhf(gg);
            float hv = sigf(go) * tanhf(cn);
            float ho = valid ? hv : h_r[r];
            float co = valid ? cn : c_r[r];
            c_r[r] = co;
            h_r[r] = ho;
            size_t oi = (size_t)b * H_SZ + hn_c;
            unsigned short hi, lo;
            bf16_split(ho, hi, lo);
            hhi_out[oi] = hi;
            hlo_out[oi] = lo;
        }

        // ---- step barrier: early-arrive, prefetch, late-wait ----
        if (t < T_LEN - 1) {
            const unsigned epoch = (unsigned)(epoch_base + t + 1);
            __threadfence();
            __syncthreads();                   // all h writes fenced
            if (tid == 0)
                *(volatile unsigned int*)&g_flag[bt][cb] = epoch;   // arrive

            // prefetch Xg for t+1 (independent of peers; hides behind skew)
            #pragma unroll
            for (int r = 0; r < 4; r++) {
                const float* xrow = g_Xg + ((size_t)(t + 1) * B_SZ + b0 + bg * 4 + r) * G_SZ;
                #pragma unroll
                for (int g = 0; g < 4; g++) xg[r][g] = xrow[g * H_SZ + hn_c];
            }

            if (tid < NCT) {                   // 16 parallel pollers
                while (*(volatile unsigned int*)&g_flag[bt][tid] < epoch)
                    __nanosleep(32);
            }
            __threadfence();
            __syncthreads();
        }
    }

    #pragma unroll
    for (int r = 0; r < 4; r++)
        g_c[(size_t)(b0 + bg * 4 + r) * H_SZ + hn_c] = c_r[r];
}

// ---------------- scoring ---------------------------------------------------
__global__ void score_norm_kernel() {
    __shared__ float sh[32];
    int b = blockIdx.x, tid = threadIdx.x;
    float e = g_c[b * H_SZ + tid];
    float n1 = sqrtf(block_sum(e * e, sh));
    float e1 = e / fmaxf(n1, 1e-12f);
    float n2 = sqrtf(block_sum(e1 * e1, sh));
    float en = e1 / fmaxf(n2, 1e-8f);
    g_E1[b * H_SZ + tid] = e1;
    g_En[b * H_SZ + tid] = en;
}

__global__ void score_centroid_kernel() {
    __shared__ float sh[32];
    int i = blockIdx.x, tid = threadIdx.x;
    float s = 0.f;
    #pragma unroll
    for (int j = 0; j < M_UTT; j++) s += g_E1[(i * M_UTT + j) * H_SZ + tid];
    float c = s * (1.f / M_UTT);
    float n = sqrtf(block_sum(c * c, sh));
    g_C[i * H_SZ + tid]  = c;
    g_Cn[i * H_SZ + tid] = c / fmaxf(n, 1e-8f);
}

__global__ void score_diag_kernel() {
    __shared__ float sh[32];
    int b = blockIdx.x, tid = threadIdx.x;
    float cm = ((float)M_UTT * g_C[(b / M_UTT) * H_SZ + tid] + g_E1[b * H_SZ + tid])
               * (1.f / (M_UTT - 1));
    float n = sqrtf(block_sum(cm * cm, sh));
    float cmn = cm / fmaxf(n, 1e-8f);
    float d = block_sum(g_En[b * H_SZ + tid] * cmn, sh);
    if (tid == 0) g_d[b] = d;
}

__global__ void score_sim_kernel(const float* __restrict__ wsim,
                                 const float* __restrict__ bsim,
                                 float* __restrict__ out)
{
    __shared__ float en[H_SZ];
    int b = blockIdx.x;
    for (int k = threadIdx.x; k < H_SZ; k += 64) en[k] = g_En[b * H_SZ + k];
    __syncthreads();
    int i = threadIdx.x;
    float dot = 0.f;
    #pragma unroll 8
    for (int k = 0; k < H_SZ; k++) dot += en[k] * g_Cn[i * H_SZ + k];
    float w = *wsim, bs = *bsim;
    float val = (i == b / M_UTT) ? g_d[b] : dot;
    out[b * N_SPK + i] = val * w + bs;
}

// ---------------- launch ----------------------------------------------------
extern "C" void kernel_launch(void* const* d_in, const int* in_sizes, int n_in,
                              void* d_out, int out_size)
{
    (void)n_in; (void)out_size;
    const float* seq  = (const float*)d_in[0];
    const int*   lens = (const int*)d_in[1];

    const float *Wih[3], *Whh[3], *bih[3], *bhh[3], *wsim, *bsim;
    if (in_sizes[2] == 1) {               // dict order (expected)
        wsim = (const float*)d_in[2];
        bsim = (const float*)d_in[3];
        for (int l = 0; l < 3; l++) {
            Wih[l] = (const float*)d_in[4 + 4 * l];
            Whh[l] = (const float*)d_in[5 + 4 * l];
            bih[l] = (const float*)d_in[6 + 4 * l];
            bhh[l] = (const float*)d_in[7 + 4 * l];
        }
    } else {
        for (int l = 0; l < 3; l++) {
            Wih[l] = (const float*)d_in[2 + 4 * l];
            Whh[l] = (const float*)d_in[3 + 4 * l];
            bih[l] = (const float*)d_in[4 + 4 * l];
            bhh[l] = (const float*)d_in[5 + 4 * l];
        }
        wsim = (const float*)d_in[14];
        bsim = (const float*)d_in[15];
    }
    float* out = (float*)d_out;

    const int pers_smem = (64 * WPB * 2 + 80 * WPB * 2) * sizeof(uint32_t);  // ~152 KB
    cudaFuncSetAttribute(lstm_persistent_kernel,
                         cudaFuncAttributeMaxDynamicSharedMemorySize, pers_smem);

    const dim3 bulk_grid(G_SZ / 64, (T_LEN * B_SZ) / 128);   // (16, 800)
    const dim3 pers_grid(NCT, NBT);                           // (16, 8)

    reset_flags_kernel<<<1, 128>>>();
    split_seq_kernel<<<(int)(((size_t)T_LEN * B_SZ * 64 + 255) / 256), 256>>>(seq);

    for (int l = 0; l < 3; l++) {
        const int K = (l == 0) ? IN_F : H_SZ;
        const int P = (l == 0) ? 64 : H_SZ;
        const int src_mode = (l == 0) ? 0 : 1;
        split_w_kernel<<<(G_SZ * P + 255) / 256, 256>>>(Wih[l], K, P);
        bulk_bf16_kernel<<<bulk_grid, 256>>>(bih[l], bhh[l], P, src_mode);
        lstm_persistent_kernel<<<pers_grid, PT, pers_smem>>>(Whh[l], lens, l * T_LEN);
    }

    score_norm_kernel<<<B_SZ, H_SZ>>>();
    score_centroid_kernel<<<N_SPK, H_SZ>>>();
    score_diag_kernel<<<B_SZ, H_SZ>>>();
    score_sim_kernel<<<B_SZ, 64>>>(wsim, bsim, out);
}

// round 15
// speedup vs baseline: 1.2850x; 1.2850x over previous
#include <cuda_runtime.h>
#include <cuda_bf16.h>
#include <math.h>
#include <stdint.h>

#define T_LEN 160
#define B_SZ  640
#define IN_F  40
#define H_SZ  256
#define G_SZ  1024
#define N_SPK 64
#define M_UTT 10

#define NBT   8        // batch tiles (recurrence)
#define BT    80       // batch rows per block
#define NCT   16       // col tiles
#define GP    68       // gate smem pitch (floats)
#define PT    320      // persistent kernel threads (10 warps)
#define WPB   132      // word pitch for bf16-pair planes (128 pairs + pad)
#define CP    20       // bulk chunk word pitch (16 words + 4 pad)

// ---------------- device scratch --------------------------------------------
static __device__ float g_Xg[(size_t)T_LEN * B_SZ * G_SZ];            // fp32 input gates
static __device__ unsigned short g_hhi[(size_t)T_LEN * B_SZ * H_SZ];  // bf16 hi h plane
static __device__ unsigned short g_hlo[(size_t)T_LEN * B_SZ * H_SZ];  // bf16 lo h plane
static __device__ unsigned short g_shi[(size_t)T_LEN * B_SZ * 64];    // layer0 seq hi (P=64)
static __device__ unsigned short g_slo[(size_t)T_LEN * B_SZ * 64];    // layer0 seq lo
static __device__ unsigned short g_Wbh[G_SZ * H_SZ];                  // W hi plane
static __device__ unsigned short g_Wbl[G_SZ * H_SZ];                  // W lo plane
static __device__ float g_c[B_SZ * H_SZ];
static __device__ float g_E1[B_SZ * H_SZ];
static __device__ float g_En[B_SZ * H_SZ];
static __device__ float g_C[N_SPK * H_SZ];
static __device__ float g_Cn[N_SPK * H_SZ];
static __device__ float g_d[B_SZ];
static __device__ unsigned int g_bar[NBT];           // per-btile step counter (R13 proven)

// ---------------- helpers ---------------------------------------------------
__device__ __forceinline__ void mma_bf16(float* d, const uint32_t* a,
                                         uint32_t b0, uint32_t b1) {
    asm volatile(
        "mma.sync.aligned.m16n8k16.row.col.f32.bf16.bf16.f32 "
        "{%0,%1,%2,%3}, {%4,%5,%6,%7}, {%8,%9}, {%0,%1,%2,%3};"
        : "+f"(d[0]), "+f"(d[1]), "+f"(d[2]), "+f"(d[3])
        : "r"(a[0]), "r"(a[1]), "r"(a[2]), "r"(a[3]), "r"(b0), "r"(b1));
}

__device__ __forceinline__ void bf16_split(float v, unsigned short& hi, unsigned short& lo) {
    __nv_bfloat16 h = __float2bfloat16(v);
    __nv_bfloat16 l = __float2bfloat16(v - __bfloat162float(h));
    hi = __bfloat16_as_ushort(h);
    lo = __bfloat16_as_ushort(l);
}

__device__ __forceinline__ float block_sum(float v, float* sh) {
    int tid = threadIdx.x;
    #pragma unroll
    for (int o = 16; o > 0; o >>= 1) v += __shfl_down_sync(0xffffffffu, v, o);
    if ((tid & 31) == 0) sh[tid >> 5] = v;
    __syncthreads();
    int nw = blockDim.x >> 5;
    float r = (tid < nw) ? sh[tid] : 0.f;
    if (tid < 32) {
        #pragma unroll
        for (int o = 16; o > 0; o >>= 1) r += __shfl_down_sync(0xffffffffu, r, o);
        if (tid == 0) sh[0] = r;
    }
    __syncthreads();
    float out = sh[0];
    __syncthreads();
    return out;
}

__device__ __forceinline__ float sigf(float x) { return 1.f / (1.f + __expf(-x)); }

__global__ void init_bar_kernel() {
    if (threadIdx.x < NBT) g_bar[threadIdx.x] = 0u;
}

// ---------------- bf16 packers ----------------------------------------------
__global__ void split_w_kernel(const float* __restrict__ W, int K, int P) {
    int idx = blockIdx.x * 256 + threadIdx.x;
    if (idx >= G_SZ * P) return;
    int row = idx / P, k = idx - row * P;
    float v = (k < K) ? W[row * K + k] : 0.f;
    unsigned short hi, lo;
    bf16_split(v, hi, lo);
    g_Wbh[idx] = hi;
    g_Wbl[idx] = lo;
}

__global__ void split_seq_kernel(const float* __restrict__ seq) {
    size_t idx = (size_t)blockIdx.x * 256 + threadIdx.x;
    if (idx >= (size_t)T_LEN * B_SZ * 64) return;
    int row = (int)(idx >> 6), k = (int)(idx & 63);
    float v = 0.f;
    if (k < IN_F) {
        int t = row / B_SZ, b = row - t * B_SZ;
        v = seq[(size_t)b * (T_LEN * IN_F) + (size_t)t * IN_F + k];
    }
    unsigned short hi, lo;
    bf16_split(v, hi, lo);
    g_shi[idx] = hi;
    g_slo[idx] = lo;
}

// ---------------- bulk GEMM, 3-term bf16 (unchanged from R13) ---------------
__global__ void __launch_bounds__(256)
bulk_bf16_kernel(const float* __restrict__ bih,
                 const float* __restrict__ bhh,
                 int P, int src_mode)
{
    __shared__ __align__(16) uint32_t Ahi[128 * CP], Alo[128 * CP];
    __shared__ __align__(16) uint32_t Bh[64 * CP],  Bl[64 * CP];

    const int tid  = threadIdx.x;
    const int warp = tid >> 5;
    const int lane = tid & 31;
    const int gid  = lane >> 2;
    const int tig  = lane & 3;
    const int row0 = blockIdx.y * 128;
    const int col0 = blockIdx.x * 64;
    const int m0   = warp * 16;

    const unsigned short* Ahg = (src_mode == 0) ? g_shi : g_hhi;
    const unsigned short* Alg = (src_mode == 0) ? g_slo : g_hlo;

    float acc[8][4];
    #pragma unroll
    for (int s = 0; s < 8; s++)
        #pragma unroll
        for (int j = 0; j < 4; j++) acc[s][j] = 0.f;

    for (int kc = 0; kc < P; kc += 32) {
        #pragma unroll
        for (int i = 0; i < 2; i++) {
            int slot = tid + i * 256;
            int r = slot >> 2, q = slot & 3;
            size_t src = (size_t)(row0 + r) * P + kc + q * 8;
            ((uint4*)&Ahi[r * CP])[q] = *(const uint4*)&Ahg[src];
            ((uint4*)&Alo[r * CP])[q] = *(const uint4*)&Alg[src];
        }
        {
            int r = tid >> 2, q = tid & 3;
            size_t src = (size_t)(col0 + r) * P + kc + q * 8;
            ((uint4*)&Bh[r * CP])[q] = *(const uint4*)&g_Wbh[src];
            ((uint4*)&Bl[r * CP])[q] = *(const uint4*)&g_Wbl[src];
        }
        __syncthreads();

        #pragma unroll
        for (int ks = 0; ks < 2; ks++) {
            const int kb = ks * 8;
            uint32_t ah[4], al[4];
            ah[0] = Ahi[(m0 + gid)     * CP + kb + tig];
            ah[1] = Ahi[(m0 + gid + 8) * CP + kb + tig];
            ah[2] = Ahi[(m0 + gid)     * CP + kb + tig + 4];
            ah[3] = Ahi[(m0 + gid + 8) * CP + kb + tig + 4];
            al[0] = Alo[(m0 + gid)     * CP + kb + tig];
            al[1] = Alo[(m0 + gid + 8) * CP + kb + tig];
            al[2] = Alo[(m0 + gid)     * CP + kb + tig + 4];
            al[3] = Alo[(m0 + gid + 8) * CP + kb + tig + 4];
            #pragma unroll
            for (int sub = 0; sub < 8; sub++) {
                int n = sub * 8 + gid;
                uint32_t bh0 = Bh[n * CP + kb + tig];
                uint32_t bh1 = Bh[n * CP + kb + tig + 4];
                uint32_t bl0 = Bl[n * CP + kb + tig];
                uint32_t bl1 = Bl[n * CP + kb + tig + 4];
                mma_bf16(acc[sub], ah, bh0, bh1);
                mma_bf16(acc[sub], al, bh0, bh1);
                mma_bf16(acc[sub], ah, bl0, bl1);
            }
        }
        __syncthreads();
    }

    #pragma unroll
    for (int sub = 0; sub < 8; sub++) {
        const int col = col0 + sub * 8 + 2 * tig;
        const float bias0 = bih[col] + bhh[col];
        const float bias1 = bih[col + 1] + bhh[col + 1];
        const int r1 = row0 + m0 + gid;
        float2 o1 = {acc[sub][0] + bias0, acc[sub][1] + bias1};
        *(float2*)&g_Xg[(size_t)r1 * G_SZ + col] = o1;
        float2 o2 = {acc[sub][2] + bias0, acc[sub][3] + bias1};
        *(float2*)&g_Xg[(size_t)(r1 + 8) * G_SZ + col] = o2;
    }
}

// ---------------- persistent LSTM recurrence, bf16 3-term -------------------
// R13 kernel (proven 5.50ms) with ONE change: the Xg[t+1] prefetch is issued
// inside the barrier shadow (between arrive and the tid-0 spin), instead of
// at the top of the next step. Barrier protocol itself is R13-verbatim.
__global__ void __launch_bounds__(PT)
lstm_persistent_kernel(const float* __restrict__ Whh,
                       const int* __restrict__ lens)
{
    extern __shared__ __align__(16) uint32_t smw[];
    uint32_t* whi = smw;                       // 64*WPB
    uint32_t* wlo = whi + 64 * WPB;
    uint32_t* hhi = wlo + 64 * WPB;            // 80*WPB
    uint32_t* hlo = hhi + 80 * WPB;
    float*    gsm = (float*)hhi;               // overlay (post-MMA staging)

    const int tid  = threadIdx.x;              // 0..319
    const int warp = tid >> 5;
    const int lane = tid & 31;
    const int gid  = lane >> 2;
    const int tig  = lane & 3;
    const int mt   = warp >> 1;
    const int nh   = warp & 1;
    const int m0   = mt * 16;

    const int n0 = blockIdx.x * 16;
    const int b0 = blockIdx.y * BT;
    const unsigned bt = blockIdx.y;

    const int hnx_c = tid & 15;
    const int bg    = tid >> 4;
    const int hn_c  = n0 + hnx_c;

    // W slice -> smem packed bf16 hi/lo pairs; col c = hx*4 + g
    for (int lin = tid; lin < 64 * 128; lin += PT) {
        int kp = lin & 127;
        int c  = lin >> 7;
        int g  = c & 3;
        int hx = c >> 2;
        const float* wr = Whh + (size_t)(g * H_SZ + n0 + hx) * H_SZ + 2 * kp;
        unsigned short h0, l0, h1, l1;
        bf16_split(wr[0], h0, l0);
        bf16_split(wr[1], h1, l1);
        whi[c * WPB + kp] = ((uint32_t)h1 << 16) | h0;
        wlo[c * WPB + kp] = ((uint32_t)l1 << 16) | l0;
    }

    int   len_r[4];
    float c_r[4], h_r[4];
    #pragma unroll
    for (int r = 0; r < 4; r++) {
        len_r[r] = lens[b0 + bg * 4 + r];
        c_r[r] = 0.f;
        h_r[r] = 0.f;
    }

    // prime Xg for t=0
    float xg[4][4];
    #pragma unroll
    for (int r = 0; r < 4; r++) {
        const float* xrow = g_Xg + ((size_t)(b0 + bg * 4 + r)) * G_SZ;
        #pragma unroll
        for (int g = 0; g < 4; g++) xg[r][g] = xrow[g * H_SZ + hn_c];
    }

    __syncthreads();

    for (int t = 0; t < T_LEN; t++) {
        if (t > 0) {
            // ---- load h_{t-1} bf16 planes [80 x 128 words] ----
            const uint4* shi = (const uint4*)(g_hhi + (size_t)(t - 1) * B_SZ * H_SZ);
            const uint4* slo = (const uint4*)(g_hlo + (size_t)(t - 1) * B_SZ * H_SZ);
            #pragma unroll
            for (int i = 0; i < 8; i++) {
                int slot = tid + i * PT;
                int b = slot >> 5;
                int q = slot & 31;
                size_t src = (size_t)(b0 + b) * 32 + q;
                ((uint4*)hhi)[b * 33 + q] = shi[src];
                ((uint4*)hlo)[b * 33 + q] = slo[src];
            }
            __syncthreads();

            float acc[4][4];
            #pragma unroll
            for (int s = 0; s < 4; s++)
                #pragma unroll
                for (int j = 0; j < 4; j++) acc[s][j] = 0.f;

            #pragma unroll 4
            for (int ks = 0; ks < 16; ks++) {
                const int kb = ks * 8;
                uint32_t ah[4], al[4];
                ah[0] = hhi[(m0 + gid)     * WPB + kb + tig];
                ah[1] = hhi[(m0 + gid + 8) * WPB + kb + tig];
                ah[2] = hhi[(m0 + gid)     * WPB + kb + tig + 4];
                ah[3] = hhi[(m0 + gid + 8) * WPB + kb + tig + 4];
                al[0] = hlo[(m0 + gid)     * WPB + kb + tig];
                al[1] = hlo[(m0 + gid + 8) * WPB + kb + tig];
                al[2] = hlo[(m0 + gid)     * WPB + kb + tig + 4];
                al[3] = hlo[(m0 + gid + 8) * WPB + kb + tig + 4];
                #pragma unroll
                for (int s = 0; s < 4; s++) {
                    int n = (nh * 4 + s) * 8 + gid;
                    uint32_t bh0 = whi[n * WPB + kb + tig];
                    uint32_t bh1 = whi[n * WPB + kb + tig + 4];
                    uint32_t bl0 = wlo[n * WPB + kb + tig];
                    uint32_t bl1 = wlo[n * WPB + kb + tig + 4];
                    mma_bf16(acc[s], ah, bh0, bh1);
                    mma_bf16(acc[s], al, bh0, bh1);
                    mma_bf16(acc[s], ah, bl0, bl1);
                }
            }
            __syncthreads();

            #pragma unroll
            for (int s = 0; s < 4; s++) {
                int nc = (nh * 4 + s) * 8 + 2 * tig;
                float2 o1 = {acc[s][0], acc[s][1]};
                float2 o2 = {acc[s][2], acc[s][3]};
                *(float2*)&gsm[(m0 + gid)     * GP + nc] = o1;
                *(float2*)&gsm[(m0 + gid + 8) * GP + nc] = o2;
            }
            __syncthreads();
        }

        // ---- cell phase (c/h register-resident); h emitted as bf16 planes ----
        unsigned short* hhi_out = g_hhi + (size_t)t * B_SZ * H_SZ;
        unsigned short* hlo_out = g_hlo + (size_t)t * B_SZ * H_SZ;
        #pragma unroll
        for (int r = 0; r < 4; r++) {
            const int b = b0 + bg * 4 + r;
            const bool valid = (t < len_r[r]);
            float gi, gf, gg, go;
            if (t > 0) {
                float4 gv = *(const float4*)&gsm[(bg * 4 + r) * GP + hnx_c * 4];
                gi = gv.x + xg[r][0];
                gf = gv.y + xg[r][1];
                gg = gv.z + xg[r][2];
                go = gv.w + xg[r][3];
            } else {
                gi = xg[r][0]; gf = xg[r][1]; gg = xg[r][2]; go = xg[r][3];
            }
            float cn = sigf(gf) * c_r[r] + sigf(gi) * tanhf(gg);
            float hv = sigf(go) * tanhf(cn);
            float ho = valid ? hv : h_r[r];
            float co = valid ? cn : c_r[r];
            c_r[r] = co;
            h_r[r] = ho;
            size_t oi = (size_t)b * H_SZ + hn_c;
            unsigned short hi, lo;
            bf16_split(ho, hi, lo);
            hhi_out[oi] = hi;
            hlo_out[oi] = lo;
        }

        // ---- per-btile barrier (R13 protocol) + Xg prefetch in shadow ----
        if (t < T_LEN - 1) {
            __threadfence();
            __syncthreads();
            if (tid == 0) atomicAdd(&g_bar[bt], 1u);     // arrive

            // prefetch Xg[t+1] while tid 0 will spin (hidden latency)
            #pragma unroll
            for (int r = 0; r < 4; r++) {
                const float* xrow = g_Xg + ((size_t)(t + 1) * B_SZ + b0 + bg * 4 + r) * G_SZ;
                #pragma unroll
                for (int g = 0; g < 4; g++) xg[r][g] = xrow[g * H_SZ + hn_c];
            }

            if (tid == 0) {                              // wait (single poller)
                const unsigned target = (unsigned)(NCT * (t + 1));
                while (*(volatile unsigned int*)&g_bar[bt] < target) __nanosleep(64);
                __threadfence();
            }
            __syncthreads();
        }
    }

    #pragma unroll
    for (int r = 0; r < 4; r++)
        g_c[(size_t)(b0 + bg * 4 + r) * H_SZ + hn_c] = c_r[r];
}

// ---------------- scoring ---------------------------------------------------
__global__ void score_norm_kernel() {
    __shared__ float sh[32];
    int b = blockIdx.x, tid = threadIdx.x;
    float e = g_c[b * H_SZ + tid];
    float n1 = sqrtf(block_sum(e * e, sh));
    float e1 = e / fmaxf(n1, 1e-12f);
    float n2 = sqrtf(block_sum(e1 * e1, sh));
    float en = e1 / fmaxf(n2, 1e-8f);
    g_E1[b * H_SZ + tid] = e1;
    g_En[b * H_SZ + tid] = en;
}

__global__ void score_centroid_kernel() {
    __shared__ float sh[32];
    int i = blockIdx.x, tid = threadIdx.x;
    float s = 0.f;
    #pragma unroll
    for (int j = 0; j < M_UTT; j++) s += g_E1[(i * M_UTT + j) * H_SZ + tid];
    float c = s * (1.f / M_UTT);
    float n = sqrtf(block_sum(c * c, sh));
    g_C[i * H_SZ + tid]  = c;
    g_Cn[i * H_SZ + tid] = c / fmaxf(n, 1e-8f);
}

__global__ void score_diag_kernel() {
    __shared__ float sh[32];
    int b = blockIdx.x, tid = threadIdx.x;
    float cm = ((float)M_UTT * g_C[(b / M_UTT) * H_SZ + tid] + g_E1[b * H_SZ + tid])
               * (1.f / (M_UTT - 1));
    float n = sqrtf(block_sum(cm * cm, sh));
    float cmn = cm / fmaxf(n, 1e-8f);
    float d = block_sum(g_En[b * H_SZ + tid] * cmn, sh);
    if (tid == 0) g_d[b] = d;
}

__global__ void score_sim_kernel(const float* __restrict__ wsim,
                                 const float* __restrict__ bsim,
                                 float* __restrict__ out)
{
    __shared__ float en[H_SZ];
    int b = blockIdx.x;
    for (int k = threadIdx.x; k < H_SZ; k += 64) en[k] = g_En[b * H_SZ + k];
    __syncthreads();
    int i = threadIdx.x;
    float dot = 0.f;
    #pragma unroll 8
    for (int k = 0; k < H_SZ; k++) dot += en[k] * g_Cn[i * H_SZ + k];
    float w = *wsim, bs = *bsim;
    float val = (i == b / M_UTT) ? g_d[b] : dot;
    out[b * N_SPK + i] = val * w + bs;
}

// ---------------- launch ----------------------------------------------------
extern "C" void kernel_launch(void* const* d_in, const int* in_sizes, int n_in,
                              void* d_out, int out_size)
{
    (void)n_in; (void)out_size;
    const float* seq  = (const float*)d_in[0];
    const int*   lens = (const int*)d_in[1];

    const float *Wih[3], *Whh[3], *bih[3], *bhh[3], *wsim, *bsim;
    if (in_sizes[2] == 1) {               // dict order (expected)
        wsim = (const float*)d_in[2];
        bsim = (const float*)d_in[3];
        for (int l = 0; l < 3; l++) {
            Wih[l] = (const float*)d_in[4 + 4 * l];
            Whh[l] = (const float*)d_in[5 + 4 * l];
            bih[l] = (const float*)d_in[6 + 4 * l];
            bhh[l] = (const float*)d_in[7 + 4 * l];
        }
    } else {
        for (int l = 0; l < 3; l++) {
            Wih[l] = (const float*)d_in[2 + 4 * l];
            Whh[l] = (const float*)d_in[3 + 4 * l];
            bih[l] = (const float*)d_in[4 + 4 * l];
            bhh[l] = (const float*)d_in[5 + 4 * l];
        }
        wsim = (const float*)d_in[14];
        bsim = (const float*)d_in[15];
    }
    float* out = (float*)d_out;

    const int pers_smem = (64 * WPB * 2 + 80 * WPB * 2) * sizeof(uint32_t);  // ~152 KB
    cudaFuncSetAttribute(lstm_persistent_kernel,
                         cudaFuncAttributeMaxDynamicSharedMemorySize, pers_smem);

    const dim3 bulk_grid(G_SZ / 64, (T_LEN * B_SZ) / 128);   // (16, 800)
    const dim3 pers_grid(NCT, NBT);                           // (16, 8)

    split_seq_kernel<<<(int)(((size_t)T_LEN * B_SZ * 64 + 255) / 256), 256>>>(seq);

    for (int l = 0; l < 3; l++) {
        const int K = (l == 0) ? IN_F : H_SZ;
        const int P = (l == 0) ? 64 : H_SZ;
        const int src_mode = (l == 0) ? 0 : 1;
        split_w_kernel<<<(G_SZ * P + 255) / 256, 256>>>(Wih[l], K, P);
        bulk_bf16_kernel<<<bulk_grid, 256>>>(bih[l], bhh[l], P, src_mode);
        init_bar_kernel<<<1, 32>>>();
        lstm_persistent_kernel<<<pers_grid, PT, pers_smem>>>(Whh[l], lens);
    }

    score_norm_kernel<<<B_SZ, H_SZ>>>();
    score_centroid_kernel<<<N_SPK, H_SZ>>>();
    score_diag_kernel<<<B_SZ, H_SZ>>>();
    score_sim_kernel<<<B_SZ, 64>>>(wsim, bsim, out);
}